// round 14
// baseline (speedup 1.0000x reference)
#include <cuda_runtime.h>
#include <cstdint>

#define DIM 16
#define HID 32
#define TPB 128
#define WARPS_PER_CTA (TPB / 32)
#define TILES_PER_WARP 16
#define DEPTH 6
#define TILE_BYTES 1024          // 16 rows x 16 f32

// ---------------- low-level helpers ----------------
__device__ __forceinline__ unsigned tf32_rna(float f) {   // init-path only
    unsigned u; asm("cvt.rna.tf32.f32 %0, %1;" : "=r"(u) : "f"(f)); return u;
}
__device__ __forceinline__ unsigned bits(float f) { return __float_as_uint(f); }

__device__ __forceinline__ unsigned smem_u32(const void* p) {
    unsigned a;
    asm("{ .reg .u64 t; cvta.to.shared.u64 t, %1; cvt.u32.u64 %0, t; }"
        : "=r"(a) : "l"(p));
    return a;
}
__device__ __forceinline__ void cp16(unsigned saddr, const void* gaddr) {
    asm volatile("cp.async.cg.shared.global [%0], [%1], 16;"
                 :: "r"(saddr), "l"(gaddr) : "memory");
}
__device__ __forceinline__ void cp_commit() {
    asm volatile("cp.async.commit_group;" ::: "memory");
}
template<int N>
__device__ __forceinline__ void cp_wait() {
    asm volatile("cp.async.wait_group %0;" :: "n"(N) : "memory");
}
__device__ __forceinline__ float4 lds128(unsigned addr) {
    float4 v;
    asm volatile("ld.shared.v4.f32 {%0,%1,%2,%3}, [%4];"
                 : "=f"(v.x), "=f"(v.y), "=f"(v.z), "=f"(v.w) : "r"(addr));
    return v;
}

__device__ __forceinline__ void mma8(float& d0, float& d1, float& d2, float& d3,
                                     unsigned a0, unsigned a1, unsigned a2, unsigned a3,
                                     unsigned b0, unsigned b1) {
    asm volatile(
        "mma.sync.aligned.m16n8k8.row.col.f32.tf32.tf32.f32 "
        "{%0,%1,%2,%3}, {%4,%5,%6,%7}, {%8,%9}, {%0,%1,%2,%3};"
        : "+f"(d0), "+f"(d1), "+f"(d2), "+f"(d3)
        : "r"(a0), "r"(a1), "r"(a2), "r"(a3), "r"(b0), "r"(b1));
}
__device__ __forceinline__ float fast_tanh(float x) {
    float r; asm("tanh.approx.f32 %0, %1;" : "=f"(r) : "f"(x)); return r;
}

union F2U { float2 f; unsigned long long u; };
__device__ __forceinline__ float2 f2fma(float2 a, float2 b, float2 c) {
    F2U A, B, C, R; A.f = a; B.f = b; C.f = c;
    asm("fma.rn.f32x2 %0, %1, %2, %3;" : "=l"(R.u) : "l"(A.u), "l"(B.u), "l"(C.u));
    return R.f;
}
__device__ __forceinline__ float2 f2mul(float2 a, float2 b) {
    F2U A, B, R; A.f = a; B.f = b;
    asm("mul.rn.f32x2 %0, %1, %2;" : "=l"(R.u) : "l"(A.u), "l"(B.u));
    return R.f;
}
__device__ __forceinline__ float2 f2add(float2 a, float2 b) {
    F2U A, B, R; A.f = a; B.f = b;
    asm("add.rn.f32x2 %0, %1, %2;" : "=l"(R.u) : "l"(A.u), "l"(B.u));
    return R.f;
}

// tanh-form GELU on a packed pair
__device__ __forceinline__ float2 gelu2(float2 x) {
    const float C1 = 0.7978845608028654f;            // sqrt(2/pi)
    const float C2 = 0.7978845608028654f * 0.044715f;
    float2 x2 = f2mul(x, x);
    float2 inner = f2fma(x2, make_float2(C2, C2), make_float2(C1, C1));
    float2 y  = f2mul(x, inner);
    float2 t  = make_float2(fast_tanh(y.x), fast_tanh(y.y));
    float2 phi = f2fma(t, make_float2(0.5f, 0.5f), make_float2(0.5f, 0.5f));
    return f2mul(x, phi);
}

struct WarpCtx {                 // LN affine folded into B1f / b1p / s1p at init
    unsigned B1f[2][4][2];
    unsigned B2f[4][2][2];
    float2 b1p[4];               // b1'[nt*8+2c], b1'[nt*8+2c+1]
    float2 s1p[4];               // s1[nt*8+2c],  s1[nt*8+2c+1]  (row-sums of W1folded)
    float2 b2p[2];
};

// Tile compute with DEFERRED LayerNorm:
//   C1_raw = x @ W1foldedT   (starts right after LDS, independent of reduction)
//   C1'    = rstd_row * C1_raw + (nmr_row * s1 + b1')
__device__ __forceinline__ void tile_compute(const WarpCtx& W,
                                             float4 xa, float4 xb,
                                             float* __restrict__ orow,
                                             int g, int c)
{
    float2 xp[4] = { make_float2(xa.x, xb.x), make_float2(xa.y, xb.y),
                     make_float2(xa.z, xb.z), make_float2(xa.w, xb.w) };

    // LN raw stats + quad reduction (runs concurrently with GEMM1 below)
    float2 s = f2add(f2add(xp[0], xp[1]), f2add(xp[2], xp[3]));
    float2 q = f2mul(xp[0], xp[0]);
    q = f2fma(xp[1], xp[1], q);
    q = f2fma(xp[2], xp[2], q);
    q = f2fma(xp[3], xp[3], q);

    s.x += __shfl_xor_sync(0xffffffffu, s.x, 1); s.x += __shfl_xor_sync(0xffffffffu, s.x, 2);
    s.y += __shfl_xor_sync(0xffffffffu, s.y, 1); s.y += __shfl_xor_sync(0xffffffffu, s.y, 2);
    q.x += __shfl_xor_sync(0xffffffffu, q.x, 1); q.x += __shfl_xor_sync(0xffffffffu, q.x, 2);
    q.y += __shfl_xor_sync(0xffffffffu, q.y, 1); q.y += __shfl_xor_sync(0xffffffffu, q.y, 2);

    // GEMM1 on RAW x, zero-seeded (independent of the shuffle chain)
    float C1[4][4];
    #pragma unroll
    for (int nt = 0; nt < 4; nt++) {
        C1[nt][0] = 0.f; C1[nt][1] = 0.f; C1[nt][2] = 0.f; C1[nt][3] = 0.f;
        mma8(C1[nt][0], C1[nt][1], C1[nt][2], C1[nt][3],
             bits(xp[0].x), bits(xp[0].y), bits(xp[1].x), bits(xp[1].y),
             W.B1f[0][nt][0], W.B1f[0][nt][1]);
        mma8(C1[nt][0], C1[nt][1], C1[nt][2], C1[nt][3],
             bits(xp[2].x), bits(xp[2].y), bits(xp[3].x), bits(xp[3].y),
             W.B1f[1][nt][0], W.B1f[1][nt][1]);
    }

    // finish the reduction
    const float inv = 1.0f / 16.0f;
    float2 mup = f2mul(s, make_float2(inv, inv));
    float2 qi  = f2mul(q, make_float2(inv, inv));
    float rstd0 = rsqrtf(fmaf(-mup.x, mup.x, qi.x) + 1e-5f);
    float rstd1 = rsqrtf(fmaf(-mup.y, mup.y, qi.y) + 1e-5f);
    float2 rsp0 = make_float2(rstd0, rstd0);
    float2 rsp1 = make_float2(rstd1, rstd1);
    float2 nm0  = make_float2(-mup.x * rstd0, -mup.x * rstd0);
    float2 nm1  = make_float2(-mup.y * rstd1, -mup.y * rstd1);

    // post-scale LN + GELU; result IS the GEMM2 A fragment
    float2 ga[4], gb[4];
    #pragma unroll
    for (int kt = 0; kt < 4; kt++) {
        float2 off0 = f2fma(nm0, W.s1p[kt], W.b1p[kt]);   // row g
        float2 off1 = f2fma(nm1, W.s1p[kt], W.b1p[kt]);   // row g+8
        float2 v0 = f2fma(rsp0, make_float2(C1[kt][0], C1[kt][1]), off0);
        float2 v1 = f2fma(rsp1, make_float2(C1[kt][2], C1[kt][3]), off1);
        ga[kt] = gelu2(v0);
        gb[kt] = gelu2(v1);
    }

    // GEMM2 (8 mma), single accumulator seeded with b2 + residual
    float C2[2][4];
    {
        float2 s00 = f2add(W.b2p[0], make_float2(xa.x, xa.y));
        float2 s01 = f2add(W.b2p[1], make_float2(xa.z, xa.w));
        float2 s10 = f2add(W.b2p[0], make_float2(xb.x, xb.y));
        float2 s11 = f2add(W.b2p[1], make_float2(xb.z, xb.w));
        C2[0][0] = s00.x; C2[0][1] = s00.y; C2[0][2] = s10.x; C2[0][3] = s10.y;
        C2[1][0] = s01.x; C2[1][1] = s01.y; C2[1][2] = s11.x; C2[1][3] = s11.y;
    }
    #pragma unroll
    for (int nt = 0; nt < 2; nt++)
        #pragma unroll
        for (int kt = 0; kt < 4; kt++)
            mma8(C2[nt][0], C2[nt][1], C2[nt][2], C2[nt][3],
                 bits(ga[kt].x), bits(gb[kt].x), bits(ga[kt].y), bits(gb[kt].y),
                 W.B2f[kt][nt][0], W.B2f[kt][nt][1]);

    *reinterpret_cast<float4*>(orow + g * DIM + 4 * c) =
        make_float4(C2[0][0], C2[0][1], C2[1][0], C2[1][1]);
    *reinterpret_cast<float4*>(orow + (g + 8) * DIM + 4 * c) =
        make_float4(C2[0][2], C2[0][3], C2[1][2], C2[1][3]);
}

// One pipeline iteration, IT compile-time so wait_group count is a literal.
template<int IT>
__device__ __forceinline__ void pipe_iter(const WarpCtx& W,
                                          const char* __restrict__ xbase,
                                          float* __restrict__ obase,
                                          unsigned sbase,
                                          int lane, int g, int c)
{
    constexpr int NW = (TILES_PER_WARP - 1 - IT < DEPTH - 1) ? (TILES_PER_WARP - 1 - IT)
                                                             : (DEPTH - 1);
    cp_wait<NW>();

    const unsigned saddr = sbase + (IT % DEPTH) * TILE_BYTES + lane * 16;
    float4 xa = lds128(saddr);
    float4 xb = lds128(saddr + 512);

    if (IT + DEPTH < TILES_PER_WARP) {
        const char* ga = xbase + (size_t)(IT + DEPTH) * TILE_BYTES + lane * 16;
        unsigned sa = sbase + (IT % DEPTH) * TILE_BYTES + lane * 16;
        cp16(sa, ga);
        cp16(sa + 512, ga + 512);
        cp_commit();
    }

    tile_compute(W, xa, xb, obase + (size_t)IT * 16 * DIM, g, c);

    if constexpr (IT + 1 < TILES_PER_WARP)
        pipe_iter<IT + 1>(W, xbase, obase, sbase, lane, g, c);
}

// ---------------- kernel ----------------
__global__ void __launch_bounds__(TPB, 5)
fused_ln_mlp_mma(const float* __restrict__ x,
                 const float* __restrict__ ln_w, const float* __restrict__ ln_b,
                 const float* __restrict__ w1,   const float* __restrict__ b1,
                 const float* __restrict__ w2,   const float* __restrict__ b2,
                 float* __restrict__ out, int ntiles)
{
    __shared__ __align__(16) char stage[WARPS_PER_CTA][DEPTH * TILE_BYTES];

    const int lane = threadIdx.x & 31;
    const int wrp  = threadIdx.x >> 5;
    const int g = lane >> 2;
    const int c = lane & 3;

    WarpCtx W;
    {
        // raw w1 fragment values (this lane holds w1[nt*8+g][4c..4c+3])
        const float4 lw = *reinterpret_cast<const float4*>(ln_w + 4 * c);
        const float4 lb = *reinterpret_cast<const float4*>(ln_b + 4 * c);
        const float lnw[4] = { lw.x, lw.y, lw.z, lw.w };
        const float lnb[4] = { lb.x, lb.y, lb.z, lb.w };

        float dot[4];   // Σ_d W1[nt*8+g][d] * ln_b[d]  (partial over this lane's 4 cols)
        float sum[4];   // Σ_d W1folded[nt*8+g][d]      (partial)
        #pragma unroll
        for (int nt = 0; nt < 4; nt++) { dot[nt] = 0.f; sum[nt] = 0.f; }

        #pragma unroll
        for (int kt = 0; kt < 2; kt++)
            #pragma unroll
            for (int nt = 0; nt < 4; nt++) {
                float w0  = w1[(nt * 8 + g) * DIM + 4 * c + 2 * kt];
                float w1v = w1[(nt * 8 + g) * DIM + 4 * c + 2 * kt + 1];
                float f0 = w0  * lnw[2 * kt];
                float f1 = w1v * lnw[2 * kt + 1];
                W.B1f[kt][nt][0] = tf32_rna(f0);
                W.B1f[kt][nt][1] = tf32_rna(f1);
                sum[nt] += f0 + f1;                                   // for s1
                dot[nt] = fmaf(w0, lnb[2 * kt], dot[nt]);             // for b1'
                dot[nt] = fmaf(w1v, lnb[2 * kt + 1], dot[nt]);
            }
        // quad-reduce over c -> full values for hidden row nt*8+g
        #pragma unroll
        for (int nt = 0; nt < 4; nt++) {
            dot[nt] += __shfl_xor_sync(0xffffffffu, dot[nt], 1);
            dot[nt] += __shfl_xor_sync(0xffffffffu, dot[nt], 2);
            sum[nt] += __shfl_xor_sync(0xffffffffu, sum[nt], 1);
            sum[nt] += __shfl_xor_sync(0xffffffffu, sum[nt], 2);
        }
        // this lane needs hidden cols h = nt*8+2c and nt*8+2c+1 (rows g'=2c, 2c+1)
        #pragma unroll
        for (int nt = 0; nt < 4; nt++) {
            float d0 = __shfl_sync(0xffffffffu, dot[nt], 8 * c);
            float d1 = __shfl_sync(0xffffffffu, dot[nt], 8 * c + 4);
            float s0 = __shfl_sync(0xffffffffu, sum[nt], 8 * c);
            float s1v = __shfl_sync(0xffffffffu, sum[nt], 8 * c + 4);
            W.b1p[nt] = make_float2(b1[nt * 8 + 2 * c] + d0,
                                    b1[nt * 8 + 2 * c + 1] + d1);
            W.s1p[nt] = make_float2(s0, s1v);
        }
    }
    #pragma unroll
    for (int nt = 0; nt < 2; nt++) {
        int od = 4 * (g >> 1) + 2 * nt + (g & 1);
        #pragma unroll
        for (int kt = 0; kt < 4; kt++) {
            W.B2f[kt][nt][0] = tf32_rna(w2[od * HID + kt * 8 + 2 * c]);
            W.B2f[kt][nt][1] = tf32_rna(w2[od * HID + kt * 8 + 2 * c + 1]);
        }
    }
    #pragma unroll
    for (int nt = 0; nt < 2; nt++)
        W.b2p[nt] = make_float2(b2[4 * c + 2 * nt], b2[4 * c + 2 * nt + 1]);

    const int gwarp = blockIdx.x * WARPS_PER_CTA + wrp;
    const long t0 = (long)gwarp * TILES_PER_WARP;
    if (t0 >= ntiles) return;

    if (t0 + TILES_PER_WARP <= ntiles) {
        // ===== fast path: cp.async depth-6 pipeline, fully unrolled =====
        const char* xbase = reinterpret_cast<const char*>(x + (size_t)t0 * 16 * DIM);
        float* obase = out + (size_t)t0 * 16 * DIM;
        const unsigned sbase = smem_u32(&stage[wrp][0]);

        #pragma unroll
        for (int i = 0; i < DEPTH; i++) {
            unsigned sa = sbase + i * TILE_BYTES + lane * 16;
            const char* ga = xbase + (size_t)i * TILE_BYTES + lane * 16;
            cp16(sa, ga);
            cp16(sa + 512, ga + 512);
            cp_commit();
        }
        pipe_iter<0>(W, xbase, obase, sbase, lane, g, c);
    } else {
        // ===== tail path (generic, rarely taken) =====
        const int n_it = (int)(ntiles - t0);
        for (int it = 0; it < n_it; ++it) {
            const float4* p = reinterpret_cast<const float4*>(
                x + (size_t)(t0 + it) * 16 * DIM);
            float4 xa = p[lane], xb = p[lane + 32];
            tile_compute(W, xa, xb, out + (size_t)(t0 + it) * 16 * DIM, g, c);
        }
    }
}

extern "C" void kernel_launch(void* const* d_in, const int* in_sizes, int n_in,
                              void* d_out, int out_size)
{
    const float* x    = (const float*)d_in[0];
    const float* ln_w = (const float*)d_in[1];
    const float* ln_b = (const float*)d_in[2];
    const float* w1   = (const float*)d_in[3];
    const float* b1   = (const float*)d_in[4];
    const float* w2   = (const float*)d_in[5];
    const float* b2   = (const float*)d_in[6];
    int nrows  = in_sizes[0] / DIM;
    int ntiles = nrows / 16;
    int tiles_per_cta = WARPS_PER_CTA * TILES_PER_WARP;
    int blocks = (ntiles + tiles_per_cta - 1) / tiles_per_cta;
    fused_ln_mlp_mma<<<blocks, TPB>>>(x, ln_w, ln_b, w1, b1, w2, b2,
                                      (float*)d_out, ntiles);
}

// round 15
// speedup vs baseline: 1.0930x; 1.0930x over previous
#include <cuda_runtime.h>
#include <cstdint>

#define DIM 16
#define HID 32
#define TPB 128
#define WARPS_PER_CTA (TPB / 32)
#define TILES_PER_WARP 16
#define DEPTH 6
#define TILE_BYTES 1024          // 16 rows x 16 f32

// ---------------- low-level helpers ----------------
__device__ __forceinline__ unsigned tf32_rna(float f) {   // init-path only
    unsigned u; asm("cvt.rna.tf32.f32 %0, %1;" : "=r"(u) : "f"(f)); return u;
}
__device__ __forceinline__ unsigned bits(float f) { return __float_as_uint(f); }

__device__ __forceinline__ unsigned smem_u32(const void* p) {
    unsigned a;
    asm("{ .reg .u64 t; cvta.to.shared.u64 t, %1; cvt.u32.u64 %0, t; }"
        : "=r"(a) : "l"(p));
    return a;
}
__device__ __forceinline__ void cp16(unsigned saddr, const void* gaddr) {
    asm volatile("cp.async.cg.shared.global [%0], [%1], 16;"
                 :: "r"(saddr), "l"(gaddr) : "memory");
}
__device__ __forceinline__ void cp_commit() {
    asm volatile("cp.async.commit_group;" ::: "memory");
}
template<int N>
__device__ __forceinline__ void cp_wait() {
    asm volatile("cp.async.wait_group %0;" :: "n"(N) : "memory");
}
__device__ __forceinline__ float4 lds128(unsigned addr) {
    float4 v;
    asm volatile("ld.shared.v4.f32 {%0,%1,%2,%3}, [%4];"
                 : "=f"(v.x), "=f"(v.y), "=f"(v.z), "=f"(v.w) : "r"(addr));
    return v;
}
__device__ __forceinline__ uint2 lds64(unsigned addr) {
    uint2 v;
    asm volatile("ld.shared.v2.u32 {%0,%1}, [%2];"
                 : "=r"(v.x), "=r"(v.y) : "r"(addr));
    return v;
}
__device__ __forceinline__ void sts64(unsigned addr, unsigned v0, unsigned v1) {
    asm volatile("st.shared.v2.u32 [%0], {%1,%2};"
                 :: "r"(addr), "r"(v0), "r"(v1) : "memory");
}

__device__ __forceinline__ void mma8(float& d0, float& d1, float& d2, float& d3,
                                     unsigned a0, unsigned a1, unsigned a2, unsigned a3,
                                     unsigned b0, unsigned b1) {
    asm volatile(
        "mma.sync.aligned.m16n8k8.row.col.f32.tf32.tf32.f32 "
        "{%0,%1,%2,%3}, {%4,%5,%6,%7}, {%8,%9}, {%0,%1,%2,%3};"
        : "+f"(d0), "+f"(d1), "+f"(d2), "+f"(d3)
        : "r"(a0), "r"(a1), "r"(a2), "r"(a3), "r"(b0), "r"(b1));
}
__device__ __forceinline__ float fast_tanh(float x) {
    float r; asm("tanh.approx.f32 %0, %1;" : "=f"(r) : "f"(x)); return r;
}

union F2U { float2 f; unsigned long long u; };
__device__ __forceinline__ float2 f2fma(float2 a, float2 b, float2 c) {
    F2U A, B, C, R; A.f = a; B.f = b; C.f = c;
    asm("fma.rn.f32x2 %0, %1, %2, %3;" : "=l"(R.u) : "l"(A.u), "l"(B.u), "l"(C.u));
    return R.f;
}
__device__ __forceinline__ float2 f2mul(float2 a, float2 b) {
    F2U A, B, R; A.f = a; B.f = b;
    asm("mul.rn.f32x2 %0, %1, %2;" : "=l"(R.u) : "l"(A.u), "l"(B.u));
    return R.f;
}
__device__ __forceinline__ float2 f2add(float2 a, float2 b) {
    F2U A, B, R; A.f = a; B.f = b;
    asm("add.rn.f32x2 %0, %1, %2;" : "=l"(R.u) : "l"(A.u), "l"(B.u));
    return R.f;
}

// tanh-form GELU on a packed pair
__device__ __forceinline__ float2 gelu2(float2 x) {
    const float C1 = 0.7978845608028654f;            // sqrt(2/pi)
    const float C2 = 0.7978845608028654f * 0.044715f;
    float2 x2 = f2mul(x, x);
    float2 inner = f2fma(x2, make_float2(C2, C2), make_float2(C1, C1));
    float2 y  = f2mul(x, inner);
    float2 t  = make_float2(fast_tanh(y.x), fast_tanh(y.y));
    float2 phi = f2fma(t, make_float2(0.5f, 0.5f), make_float2(0.5f, 0.5f));
    return f2mul(x, phi);
}

struct WarpCtx {                 // LN affine folded into B1f/b1v at init
    unsigned B1f[2][4][2];       // GEMM1 B-fragments stay in registers
    float b1v[4][2];
    float2 b2p[2];
};

// Full tile compute. GEMM2 B-fragments are loaded just-in-time from CTA-shared
// memory (sb2l = base + lane*8): 8x conflict-free LDS.64, transient registers.
__device__ __forceinline__ void tile_compute(const WarpCtx& W,
                                             float4 xa, float4 xb,
                                             float* __restrict__ orow,
                                             unsigned sb2l,
                                             int g, int c)
{
    float2 xp[4] = { make_float2(xa.x, xb.x), make_float2(xa.y, xb.y),
                     make_float2(xa.z, xb.z), make_float2(xa.w, xb.w) };

    float2 s = f2add(f2add(xp[0], xp[1]), f2add(xp[2], xp[3]));
    float2 q = f2mul(xp[0], xp[0]);
    q = f2fma(xp[1], xp[1], q);
    q = f2fma(xp[2], xp[2], q);
    q = f2fma(xp[3], xp[3], q);

    s.x += __shfl_xor_sync(0xffffffffu, s.x, 1); s.x += __shfl_xor_sync(0xffffffffu, s.x, 2);
    s.y += __shfl_xor_sync(0xffffffffu, s.y, 1); s.y += __shfl_xor_sync(0xffffffffu, s.y, 2);
    q.x += __shfl_xor_sync(0xffffffffu, q.x, 1); q.x += __shfl_xor_sync(0xffffffffu, q.x, 2);
    q.y += __shfl_xor_sync(0xffffffffu, q.y, 1); q.y += __shfl_xor_sync(0xffffffffu, q.y, 2);

    const float inv = 1.0f / 16.0f;
    float2 mup = f2mul(s, make_float2(inv, inv));
    float2 qi  = f2mul(q, make_float2(inv, inv));
    float rstd0 = rsqrtf(fmaf(-mup.x, mup.x, qi.x) + 1e-5f);
    float rstd1 = rsqrtf(fmaf(-mup.y, mup.y, qi.y) + 1e-5f);
    float2 rstdp = make_float2(rstd0, rstd1);
    float2 nmup  = make_float2(-mup.x * rstd0, -mup.y * rstd1);

    // LN affine folded into weights: xn = (x - mu) * rstd only
    float2 xn[4];
    #pragma unroll
    for (int j = 0; j < 4; j++)
        xn[j] = f2fma(xp[j], rstdp, nmup);

    // GEMM1 (8 mma), seeded with folded b1'
    float C1[4][4];
    #pragma unroll
    for (int nt = 0; nt < 4; nt++) {
        C1[nt][0] = W.b1v[nt][0]; C1[nt][1] = W.b1v[nt][1];
        C1[nt][2] = W.b1v[nt][0]; C1[nt][3] = W.b1v[nt][1];
        mma8(C1[nt][0], C1[nt][1], C1[nt][2], C1[nt][3],
             bits(xn[0].x), bits(xn[0].y), bits(xn[1].x), bits(xn[1].y),
             W.B1f[0][nt][0], W.B1f[0][nt][1]);
        mma8(C1[nt][0], C1[nt][1], C1[nt][2], C1[nt][3],
             bits(xn[2].x), bits(xn[2].y), bits(xn[3].x), bits(xn[3].y),
             W.B1f[1][nt][0], W.B1f[1][nt][1]);
    }

    // GELU; C1 fragment IS the GEMM2 A fragment
    float2 ga[4], gb[4];
    #pragma unroll
    for (int kt = 0; kt < 4; kt++) {
        ga[kt] = gelu2(make_float2(C1[kt][0], C1[kt][1]));   // row g
        gb[kt] = gelu2(make_float2(C1[kt][2], C1[kt][3]));   // row g+8
    }

    // GEMM2 (8 mma), single accumulator seeded with b2 + residual.
    // B-fragments streamed from CTA-shared memory (slot (kt*2+nt): 256B apart).
    float C2[2][4];
    {
        float2 s00 = f2add(W.b2p[0], make_float2(xa.x, xa.y));
        float2 s01 = f2add(W.b2p[1], make_float2(xa.z, xa.w));
        float2 s10 = f2add(W.b2p[0], make_float2(xb.x, xb.y));
        float2 s11 = f2add(W.b2p[1], make_float2(xb.z, xb.w));
        C2[0][0] = s00.x; C2[0][1] = s00.y; C2[0][2] = s10.x; C2[0][3] = s10.y;
        C2[1][0] = s01.x; C2[1][1] = s01.y; C2[1][2] = s11.x; C2[1][3] = s11.y;
    }
    #pragma unroll
    for (int nt = 0; nt < 2; nt++)
        #pragma unroll
        for (int kt = 0; kt < 4; kt++) {
            uint2 bb = lds64(sb2l + (unsigned)((kt * 2 + nt) * 256));
            mma8(C2[nt][0], C2[nt][1], C2[nt][2], C2[nt][3],
                 bits(ga[kt].x), bits(gb[kt].x), bits(ga[kt].y), bits(gb[kt].y),
                 bb.x, bb.y);
        }

    *reinterpret_cast<float4*>(orow + g * DIM + 4 * c) =
        make_float4(C2[0][0], C2[0][1], C2[1][0], C2[1][1]);
    *reinterpret_cast<float4*>(orow + (g + 8) * DIM + 4 * c) =
        make_float4(C2[0][2], C2[0][3], C2[1][2], C2[1][3]);
}

// One pipeline iteration, IT compile-time so wait_group count is a literal.
template<int IT>
__device__ __forceinline__ void pipe_iter(const WarpCtx& W,
                                          const char* __restrict__ xbase,
                                          float* __restrict__ obase,
                                          unsigned sbase, unsigned sb2l,
                                          int lane, int g, int c)
{
    constexpr int NW = (TILES_PER_WARP - 1 - IT < DEPTH - 1) ? (TILES_PER_WARP - 1 - IT)
                                                             : (DEPTH - 1);
    cp_wait<NW>();

    const unsigned saddr = sbase + (IT % DEPTH) * TILE_BYTES + lane * 16;
    float4 xa = lds128(saddr);
    float4 xb = lds128(saddr + 512);

    if (IT + DEPTH < TILES_PER_WARP) {
        const char* ga = xbase + (size_t)(IT + DEPTH) * TILE_BYTES + lane * 16;
        unsigned sa = sbase + (IT % DEPTH) * TILE_BYTES + lane * 16;
        cp16(sa, ga);
        cp16(sa + 512, ga + 512);
        cp_commit();
    }

    tile_compute(W, xa, xb, obase + (size_t)IT * 16 * DIM, sb2l, g, c);

    if constexpr (IT + 1 < TILES_PER_WARP)
        pipe_iter<IT + 1>(W, xbase, obase, sbase, sb2l, lane, g, c);
}

// ---------------- kernel ----------------
__global__ void __launch_bounds__(TPB, 6)
fused_ln_mlp_mma(const float* __restrict__ x,
                 const float* __restrict__ ln_w, const float* __restrict__ ln_b,
                 const float* __restrict__ w1,   const float* __restrict__ b1,
                 const float* __restrict__ w2,   const float* __restrict__ b2,
                 float* __restrict__ out, int ntiles)
{
    __shared__ __align__(16) char stage[WARPS_PER_CTA][DEPTH * TILE_BYTES];
    __shared__ __align__(16) uint2 sB2[8][32];   // [kt*2+nt][lane], 2 KB, CTA-shared

    const int lane = threadIdx.x & 31;
    const int wrp  = threadIdx.x >> 5;
    const int g = lane >> 2;
    const int c = lane & 3;

    WarpCtx W;
    {
        // raw w1 fragment values (this lane holds w1[nt*8+g][4c..4c+3])
        const float4 lw = *reinterpret_cast<const float4*>(ln_w + 4 * c);
        const float4 lb = *reinterpret_cast<const float4*>(ln_b + 4 * c);
        const float lnw[4] = { lw.x, lw.y, lw.z, lw.w };
        const float lnb[4] = { lb.x, lb.y, lb.z, lb.w };

        float dot[4];                       // Σ_d w1[nt*8+g][d] * ln_b[d] (partial)
        #pragma unroll
        for (int nt = 0; nt < 4; nt++) dot[nt] = 0.f;

        #pragma unroll
        for (int kt = 0; kt < 2; kt++)
            #pragma unroll
            for (int nt = 0; nt < 4; nt++) {
                float w0 = w1[(nt * 8 + g) * DIM + 4 * c + 2 * kt];
                float w1v = w1[(nt * 8 + g) * DIM + 4 * c + 2 * kt + 1];
                W.B1f[kt][nt][0] = tf32_rna(w0 * lnw[2 * kt]);       // fold ln_w
                W.B1f[kt][nt][1] = tf32_rna(w1v * lnw[2 * kt + 1]);
                dot[nt] = fmaf(w0, lnb[2 * kt], dot[nt]);            // fold ln_b
                dot[nt] = fmaf(w1v, lnb[2 * kt + 1], dot[nt]);
            }
        // quad-reduce dot over c -> full dot for hidden row nt*8+g
        #pragma unroll
        for (int nt = 0; nt < 4; nt++) {
            dot[nt] += __shfl_xor_sync(0xffffffffu, dot[nt], 1);
            dot[nt] += __shfl_xor_sync(0xffffffffu, dot[nt], 2);
        }
        // b1'[h] = b1[h] + dot[h]; this lane needs h = nt*8+2c and nt*8+2c+1
        #pragma unroll
        for (int nt = 0; nt < 4; nt++) {
            float d0 = __shfl_sync(0xffffffffu, dot[nt], 8 * c);       // g' = 2c
            float d1 = __shfl_sync(0xffffffffu, dot[nt], 8 * c + 4);   // g' = 2c+1
            W.b1v[nt][0] = b1[nt * 8 + 2 * c] + d0;
            W.b1v[nt][1] = b1[nt * 8 + 2 * c + 1] + d1;
        }
    }

    // GEMM2 B-fragments: warp-invariant (lane-indexed only) -> compute in warp 0,
    // store once to CTA-shared memory.
    const unsigned sb2base = smem_u32(&sB2[0][0]);
    if (wrp == 0) {
        #pragma unroll
        for (int nt = 0; nt < 2; nt++) {
            int od = 4 * (g >> 1) + 2 * nt + (g & 1);
            #pragma unroll
            for (int kt = 0; kt < 4; kt++) {
                unsigned v0 = tf32_rna(w2[od * HID + kt * 8 + 2 * c]);
                unsigned v1 = tf32_rna(w2[od * HID + kt * 8 + 2 * c + 1]);
                sts64(sb2base + (unsigned)((kt * 2 + nt) * 256 + lane * 8), v0, v1);
            }
        }
    }
    #pragma unroll
    for (int nt = 0; nt < 2; nt++)
        W.b2p[nt] = make_float2(b2[4 * c + 2 * nt], b2[4 * c + 2 * nt + 1]);

    __syncthreads();    // sB2 visible to all warps (before any early return)

    const unsigned sb2l = sb2base + lane * 8;
    const int gwarp = blockIdx.x * WARPS_PER_CTA + wrp;
    const long t0 = (long)gwarp * TILES_PER_WARP;
    if (t0 >= ntiles) return;

    if (t0 + TILES_PER_WARP <= ntiles) {
        // ===== fast path: cp.async depth-6 pipeline, fully unrolled =====
        const char* xbase = reinterpret_cast<const char*>(x + (size_t)t0 * 16 * DIM);
        float* obase = out + (size_t)t0 * 16 * DIM;
        const unsigned sbase = smem_u32(&stage[wrp][0]);

        #pragma unroll
        for (int i = 0; i < DEPTH; i++) {
            unsigned sa = sbase + i * TILE_BYTES + lane * 16;
            const char* ga = xbase + (size_t)i * TILE_BYTES + lane * 16;
            cp16(sa, ga);
            cp16(sa + 512, ga + 512);
            cp_commit();
        }
        pipe_iter<0>(W, xbase, obase, sbase, sb2l, lane, g, c);
    } else {
        // ===== tail path (generic, rarely taken) =====
        const int n_it = (int)(ntiles - t0);
        for (int it = 0; it < n_it; ++it) {
            const float4* p = reinterpret_cast<const float4*>(
                x + (size_t)(t0 + it) * 16 * DIM);
            float4 xa = p[lane], xb = p[lane + 32];
            tile_compute(W, xa, xb, out + (size_t)(t0 + it) * 16 * DIM, sb2l, g, c);
        }
    }
}

extern "C" void kernel_launch(void* const* d_in, const int* in_sizes, int n_in,
                              void* d_out, int out_size)
{
    const float* x    = (const float*)d_in[0];
    const float* ln_w = (const float*)d_in[1];
    const float* ln_b = (const float*)d_in[2];
    const float* w1   = (const float*)d_in[3];
    const float* b1   = (const float*)d_in[4];
    const float* w2   = (const float*)d_in[5];
    const float* b2   = (const float*)d_in[6];
    int nrows  = in_sizes[0] / DIM;
    int ntiles = nrows / 16;
    int tiles_per_cta = WARPS_PER_CTA * TILES_PER_WARP;
    int blocks = (ntiles + tiles_per_cta - 1) / tiles_per_cta;
    fused_ln_mlp_mma<<<blocks, TPB>>>(x, ln_w, ln_b, w1, b1, w2, b2,
                                      (float*)d_out, ntiles);
}

// round 16
// speedup vs baseline: 1.1076x; 1.0133x over previous
#include <cuda_runtime.h>
#include <cstdint>

#define DIM 16
#define HID 32
#define TPB 128
#define WARPS_PER_CTA (TPB / 32)
#define TILES_PER_WARP 16
#define DEPTH 8
#define TILE_BYTES 1024          // 16 rows x 16 f32

// ---------------- low-level helpers ----------------
__device__ __forceinline__ unsigned tf32_rna(float f) {   // init-path only
    unsigned u; asm("cvt.rna.tf32.f32 %0, %1;" : "=r"(u) : "f"(f)); return u;
}
__device__ __forceinline__ unsigned bits(float f) { return __float_as_uint(f); }

__device__ __forceinline__ unsigned smem_u32(const void* p) {
    unsigned a;
    asm("{ .reg .u64 t; cvta.to.shared.u64 t, %1; cvt.u32.u64 %0, t; }"
        : "=r"(a) : "l"(p));
    return a;
}
__device__ __forceinline__ void cp16(unsigned saddr, const void* gaddr) {
    asm volatile("cp.async.cg.shared.global [%0], [%1], 16;"
                 :: "r"(saddr), "l"(gaddr) : "memory");
}
__device__ __forceinline__ void cp_commit() {
    asm volatile("cp.async.commit_group;" ::: "memory");
}
template<int N>
__device__ __forceinline__ void cp_wait() {
    asm volatile("cp.async.wait_group %0;" :: "n"(N) : "memory");
}
__device__ __forceinline__ float4 lds128(unsigned addr) {
    float4 v;
    asm volatile("ld.shared.v4.f32 {%0,%1,%2,%3}, [%4];"
                 : "=f"(v.x), "=f"(v.y), "=f"(v.z), "=f"(v.w) : "r"(addr));
    return v;
}
// streaming (evict-first) 128-bit global store
__device__ __forceinline__ void stg_cs128(float* p, float a, float b, float c2, float d) {
    asm volatile("st.global.cs.v4.f32 [%0], {%1,%2,%3,%4};"
                 :: "l"(p), "f"(a), "f"(b), "f"(c2), "f"(d) : "memory");
}

__device__ __forceinline__ void mma8(float& d0, float& d1, float& d2, float& d3,
                                     unsigned a0, unsigned a1, unsigned a2, unsigned a3,
                                     unsigned b0, unsigned b1) {
    asm volatile(
        "mma.sync.aligned.m16n8k8.row.col.f32.tf32.tf32.f32 "
        "{%0,%1,%2,%3}, {%4,%5,%6,%7}, {%8,%9}, {%0,%1,%2,%3};"
        : "+f"(d0), "+f"(d1), "+f"(d2), "+f"(d3)
        : "r"(a0), "r"(a1), "r"(a2), "r"(a3), "r"(b0), "r"(b1));
}
__device__ __forceinline__ float fast_tanh(float x) {
    float r; asm("tanh.approx.f32 %0, %1;" : "=f"(r) : "f"(x)); return r;
}

union F2U { float2 f; unsigned long long u; };
__device__ __forceinline__ float2 f2fma(float2 a, float2 b, float2 c) {
    F2U A, B, C, R; A.f = a; B.f = b; C.f = c;
    asm("fma.rn.f32x2 %0, %1, %2, %3;" : "=l"(R.u) : "l"(A.u), "l"(B.u), "l"(C.u));
    return R.f;
}
__device__ __forceinline__ float2 f2mul(float2 a, float2 b) {
    F2U A, B, R; A.f = a; B.f = b;
    asm("mul.rn.f32x2 %0, %1, %2;" : "=l"(R.u) : "l"(A.u), "l"(B.u));
    return R.f;
}
__device__ __forceinline__ float2 f2add(float2 a, float2 b) {
    F2U A, B, R; A.f = a; B.f = b;
    asm("add.rn.f32x2 %0, %1, %2;" : "=l"(R.u) : "l"(A.u), "l"(B.u));
    return R.f;
}

// tanh-form GELU on a packed pair
__device__ __forceinline__ float2 gelu2(float2 x) {
    const float C1 = 0.7978845608028654f;            // sqrt(2/pi)
    const float C2 = 0.7978845608028654f * 0.044715f;
    float2 x2 = f2mul(x, x);
    float2 inner = f2fma(x2, make_float2(C2, C2), make_float2(C1, C1));
    float2 y  = f2mul(x, inner);
    float2 t  = make_float2(fast_tanh(y.x), fast_tanh(y.y));
    float2 phi = f2fma(t, make_float2(0.5f, 0.5f), make_float2(0.5f, 0.5f));
    return f2mul(x, phi);
}

struct WarpCtx {                 // LN affine folded into B1f/b1v at init
    unsigned B1f[2][4][2];
    unsigned B2f[4][2][2];
    float b1v[4][2];
    float2 b2p[2];
};

// Full tile compute: stats -> reduction -> LN -> GEMM1 -> GELU -> GEMM2 -> store.
__device__ __forceinline__ void tile_compute(const WarpCtx& W,
                                             float4 xa, float4 xb,
                                             float* __restrict__ orow,
                                             int g, int c)
{
    float2 xp[4] = { make_float2(xa.x, xb.x), make_float2(xa.y, xb.y),
                     make_float2(xa.z, xb.z), make_float2(xa.w, xb.w) };

    float2 s = f2add(f2add(xp[0], xp[1]), f2add(xp[2], xp[3]));
    float2 q = f2mul(xp[0], xp[0]);
    q = f2fma(xp[1], xp[1], q);
    q = f2fma(xp[2], xp[2], q);
    q = f2fma(xp[3], xp[3], q);

    s.x += __shfl_xor_sync(0xffffffffu, s.x, 1); s.x += __shfl_xor_sync(0xffffffffu, s.x, 2);
    s.y += __shfl_xor_sync(0xffffffffu, s.y, 1); s.y += __shfl_xor_sync(0xffffffffu, s.y, 2);
    q.x += __shfl_xor_sync(0xffffffffu, q.x, 1); q.x += __shfl_xor_sync(0xffffffffu, q.x, 2);
    q.y += __shfl_xor_sync(0xffffffffu, q.y, 1); q.y += __shfl_xor_sync(0xffffffffu, q.y, 2);

    const float inv = 1.0f / 16.0f;
    float2 mup = f2mul(s, make_float2(inv, inv));
    float2 qi  = f2mul(q, make_float2(inv, inv));
    float rstd0 = rsqrtf(fmaf(-mup.x, mup.x, qi.x) + 1e-5f);
    float rstd1 = rsqrtf(fmaf(-mup.y, mup.y, qi.y) + 1e-5f);
    float2 rstdp = make_float2(rstd0, rstd1);
    float2 nmup  = make_float2(-mup.x * rstd0, -mup.y * rstd1);

    // LN affine folded into weights: xn = (x - mu) * rstd only
    float2 xn[4];
    #pragma unroll
    for (int j = 0; j < 4; j++)
        xn[j] = f2fma(xp[j], rstdp, nmup);

    // GEMM1 (8 mma), seeded with folded b1'
    float C1[4][4];
    #pragma unroll
    for (int nt = 0; nt < 4; nt++) {
        C1[nt][0] = W.b1v[nt][0]; C1[nt][1] = W.b1v[nt][1];
        C1[nt][2] = W.b1v[nt][0]; C1[nt][3] = W.b1v[nt][1];
        mma8(C1[nt][0], C1[nt][1], C1[nt][2], C1[nt][3],
             bits(xn[0].x), bits(xn[0].y), bits(xn[1].x), bits(xn[1].y),
             W.B1f[0][nt][0], W.B1f[0][nt][1]);
        mma8(C1[nt][0], C1[nt][1], C1[nt][2], C1[nt][3],
             bits(xn[2].x), bits(xn[2].y), bits(xn[3].x), bits(xn[3].y),
             W.B1f[1][nt][0], W.B1f[1][nt][1]);
    }

    // GELU; C1 fragment IS the GEMM2 A fragment
    float2 ga[4], gb[4];
    #pragma unroll
    for (int kt = 0; kt < 4; kt++) {
        ga[kt] = gelu2(make_float2(C1[kt][0], C1[kt][1]));   // row g
        gb[kt] = gelu2(make_float2(C1[kt][2], C1[kt][3]));   // row g+8
    }

    // GEMM2 (8 mma), single accumulator seeded with b2 + residual
    float C2[2][4];
    {
        float2 s00 = f2add(W.b2p[0], make_float2(xa.x, xa.y));
        float2 s01 = f2add(W.b2p[1], make_float2(xa.z, xa.w));
        float2 s10 = f2add(W.b2p[0], make_float2(xb.x, xb.y));
        float2 s11 = f2add(W.b2p[1], make_float2(xb.z, xb.w));
        C2[0][0] = s00.x; C2[0][1] = s00.y; C2[0][2] = s10.x; C2[0][3] = s10.y;
        C2[1][0] = s01.x; C2[1][1] = s01.y; C2[1][2] = s11.x; C2[1][3] = s11.y;
    }
    #pragma unroll
    for (int nt = 0; nt < 2; nt++)
        #pragma unroll
        for (int kt = 0; kt < 4; kt++)
            mma8(C2[nt][0], C2[nt][1], C2[nt][2], C2[nt][3],
                 bits(ga[kt].x), bits(gb[kt].x), bits(ga[kt].y), bits(gb[kt].y),
                 W.B2f[kt][nt][0], W.B2f[kt][nt][1]);

    // streaming stores (evict-first): keep L2 for the read-ahead stream
    stg_cs128(orow + g * DIM + 4 * c,       C2[0][0], C2[0][1], C2[1][0], C2[1][1]);
    stg_cs128(orow + (g + 8) * DIM + 4 * c, C2[0][2], C2[0][3], C2[1][2], C2[1][3]);
}

// One pipeline iteration, IT compile-time so wait_group count is a literal.
template<int IT>
__device__ __forceinline__ void pipe_iter(const WarpCtx& W,
                                          const char* __restrict__ xbase,
                                          float* __restrict__ obase,
                                          unsigned sbase,
                                          int lane, int g, int c)
{
    constexpr int NW = (TILES_PER_WARP - 1 - IT < DEPTH - 1) ? (TILES_PER_WARP - 1 - IT)
                                                             : (DEPTH - 1);
    cp_wait<NW>();

    const unsigned saddr = sbase + (IT % DEPTH) * TILE_BYTES + lane * 16;
    float4 xa = lds128(saddr);
    float4 xb = lds128(saddr + 512);

    if (IT + DEPTH < TILES_PER_WARP) {
        const char* ga = xbase + (size_t)(IT + DEPTH) * TILE_BYTES + lane * 16;
        unsigned sa = sbase + (IT % DEPTH) * TILE_BYTES + lane * 16;
        cp16(sa, ga);
        cp16(sa + 512, ga + 512);
        cp_commit();
    }

    tile_compute(W, xa, xb, obase + (size_t)IT * 16 * DIM, g, c);

    if constexpr (IT + 1 < TILES_PER_WARP)
        pipe_iter<IT + 1>(W, xbase, obase, sbase, lane, g, c);
}

// ---------------- kernel ----------------
__global__ void __launch_bounds__(TPB, 5)
fused_ln_mlp_mma(const float* __restrict__ x,
                 const float* __restrict__ ln_w, const float* __restrict__ ln_b,
                 const float* __restrict__ w1,   const float* __restrict__ b1,
                 const float* __restrict__ w2,   const float* __restrict__ b2,
                 float* __restrict__ out, int ntiles)
{
    __shared__ __align__(16) char stage[WARPS_PER_CTA][DEPTH * TILE_BYTES];

    const int lane = threadIdx.x & 31;
    const int wrp  = threadIdx.x >> 5;
    const int g = lane >> 2;
    const int c = lane & 3;

    WarpCtx W;
    {
        // raw w1 fragment values (this lane holds w1[nt*8+g][4c..4c+3])
        const float4 lw = *reinterpret_cast<const float4*>(ln_w + 4 * c);
        const float4 lb = *reinterpret_cast<const float4*>(ln_b + 4 * c);
        const float lnw[4] = { lw.x, lw.y, lw.z, lw.w };
        const float lnb[4] = { lb.x, lb.y, lb.z, lb.w };

        float dot[4];                       // Σ_d w1[nt*8+g][d] * ln_b[d] (partial)
        #pragma unroll
        for (int nt = 0; nt < 4; nt++) dot[nt] = 0.f;

        #pragma unroll
        for (int kt = 0; kt < 2; kt++)
            #pragma unroll
            for (int nt = 0; nt < 4; nt++) {
                float w0 = w1[(nt * 8 + g) * DIM + 4 * c + 2 * kt];
                float w1v = w1[(nt * 8 + g) * DIM + 4 * c + 2 * kt + 1];
                W.B1f[kt][nt][0] = tf32_rna(w0 * lnw[2 * kt]);       // fold ln_w
                W.B1f[kt][nt][1] = tf32_rna(w1v * lnw[2 * kt + 1]);
                dot[nt] = fmaf(w0, lnb[2 * kt], dot[nt]);            // fold ln_b
                dot[nt] = fmaf(w1v, lnb[2 * kt + 1], dot[nt]);
            }
        // quad-reduce dot over c -> full dot for hidden row nt*8+g
        #pragma unroll
        for (int nt = 0; nt < 4; nt++) {
            dot[nt] += __shfl_xor_sync(0xffffffffu, dot[nt], 1);
            dot[nt] += __shfl_xor_sync(0xffffffffu, dot[nt], 2);
        }
        // b1'[h] = b1[h] + dot[h]; this lane needs h = nt*8+2c and nt*8+2c+1
        #pragma unroll
        for (int nt = 0; nt < 4; nt++) {
            float d0 = __shfl_sync(0xffffffffu, dot[nt], 8 * c);       // g' = 2c
            float d1 = __shfl_sync(0xffffffffu, dot[nt], 8 * c + 4);   // g' = 2c+1
            W.b1v[nt][0] = b1[nt * 8 + 2 * c] + d0;
            W.b1v[nt][1] = b1[nt * 8 + 2 * c + 1] + d1;
        }
    }
    #pragma unroll
    for (int nt = 0; nt < 2; nt++) {
        int od = 4 * (g >> 1) + 2 * nt + (g & 1);
        #pragma unroll
        for (int kt = 0; kt < 4; kt++) {
            W.B2f[kt][nt][0] = tf32_rna(w2[od * HID + kt * 8 + 2 * c]);
            W.B2f[kt][nt][1] = tf32_rna(w2[od * HID + kt * 8 + 2 * c + 1]);
        }
    }
    #pragma unroll
    for (int nt = 0; nt < 2; nt++)
        W.b2p[nt] = make_float2(b2[4 * c + 2 * nt], b2[4 * c + 2 * nt + 1]);

    const int gwarp = blockIdx.x * WARPS_PER_CTA + wrp;
    const long t0 = (long)gwarp * TILES_PER_WARP;
    if (t0 >= ntiles) return;

    if (t0 + TILES_PER_WARP <= ntiles) {
        // ===== fast path: cp.async depth-8 pipeline, fully unrolled =====
        const char* xbase = reinterpret_cast<const char*>(x + (size_t)t0 * 16 * DIM);
        float* obase = out + (size_t)t0 * 16 * DIM;
        const unsigned sbase = smem_u32(&stage[wrp][0]);

        #pragma unroll
        for (int i = 0; i < DEPTH; i++) {
            unsigned sa = sbase + i * TILE_BYTES + lane * 16;
            const char* ga = xbase + (size_t)i * TILE_BYTES + lane * 16;
            cp16(sa, ga);
            cp16(sa + 512, ga + 512);
            cp_commit();
        }
        pipe_iter<0>(W, xbase, obase, sbase, lane, g, c);
    } else {
        // ===== tail path (generic, rarely taken) =====
        const int n_it = (int)(ntiles - t0);
        for (int it = 0; it < n_it; ++it) {
            const float4* p = reinterpret_cast<const float4*>(
                x + (size_t)(t0 + it) * 16 * DIM);
            float4 xa = p[lane], xb = p[lane + 32];
            tile_compute(W, xa, xb, out + (size_t)(t0 + it) * 16 * DIM, g, c);
        }
    }
}

extern "C" void kernel_launch(void* const* d_in, const int* in_sizes, int n_in,
                              void* d_out, int out_size)
{
    const float* x    = (const float*)d_in[0];
    const float* ln_w = (const float*)d_in[1];
    const float* ln_b = (const float*)d_in[2];
    const float* w1   = (const float*)d_in[3];
    const float* b1   = (const float*)d_in[4];
    const float* w2   = (const float*)d_in[5];
    const float* b2   = (const float*)d_in[6];
    int nrows  = in_sizes[0] / DIM;
    int ntiles = nrows / 16;
    int tiles_per_cta = WARPS_PER_CTA * TILES_PER_WARP;
    int blocks = (ntiles + tiles_per_cta - 1) / tiles_per_cta;
    fused_ln_mlp_mma<<<blocks, TPB>>>(x, ln_w, ln_b, w1, b1, w2, b2,
                                      (float*)d_out, ntiles);
}

// round 17
// speedup vs baseline: 1.1488x; 1.0372x over previous
#include <cuda_runtime.h>
#include <cstdint>

#define DIM 16
#define HID 32
#define TPB 128
#define WARPS_PER_CTA (TPB / 32)
#define TILES_PER_WARP 16
#define DEPTH 6
#define TILE_BYTES 1024          // 16 rows x 16 f32

// ---------------- low-level helpers ----------------
__device__ __forceinline__ unsigned tf32_rna(float f) {   // init-path only
    unsigned u; asm("cvt.rna.tf32.f32 %0, %1;" : "=r"(u) : "f"(f)); return u;
}
__device__ __forceinline__ unsigned bits(float f) { return __float_as_uint(f); }

__device__ __forceinline__ unsigned smem_u32(const void* p) {
    unsigned a;
    asm("{ .reg .u64 t; cvta.to.shared.u64 t, %1; cvt.u32.u64 %0, t; }"
        : "=r"(a) : "l"(p));
    return a;
}
__device__ __forceinline__ void cp16(unsigned saddr, const void* gaddr) {
    asm volatile("cp.async.cg.shared.global [%0], [%1], 16;"
                 :: "r"(saddr), "l"(gaddr) : "memory");
}
__device__ __forceinline__ void cp_commit() {
    asm volatile("cp.async.commit_group;" ::: "memory");
}
template<int N>
__device__ __forceinline__ void cp_wait() {
    asm volatile("cp.async.wait_group %0;" :: "n"(N) : "memory");
}
__device__ __forceinline__ float4 lds128(unsigned addr) {
    float4 v;
    asm volatile("ld.shared.v4.f32 {%0,%1,%2,%3}, [%4];"
                 : "=f"(v.x), "=f"(v.y), "=f"(v.z), "=f"(v.w) : "r"(addr));
    return v;
}
// streaming (evict-first) 128-bit global store
__device__ __forceinline__ void stg_cs128(float* p, float a, float b, float c2, float d) {
    asm volatile("st.global.cs.v4.f32 [%0], {%1,%2,%3,%4};"
                 :: "l"(p), "f"(a), "f"(b), "f"(c2), "f"(d) : "memory");
}

__device__ __forceinline__ void mma8(float& d0, float& d1, float& d2, float& d3,
                                     unsigned a0, unsigned a1, unsigned a2, unsigned a3,
                                     unsigned b0, unsigned b1) {
    asm volatile(
        "mma.sync.aligned.m16n8k8.row.col.f32.tf32.tf32.f32 "
        "{%0,%1,%2,%3}, {%4,%5,%6,%7}, {%8,%9}, {%0,%1,%2,%3};"
        : "+f"(d0), "+f"(d1), "+f"(d2), "+f"(d3)
        : "r"(a0), "r"(a1), "r"(a2), "r"(a3), "r"(b0), "r"(b1));
}
__device__ __forceinline__ float fast_tanh(float x) {
    float r; asm("tanh.approx.f32 %0, %1;" : "=f"(r) : "f"(x)); return r;
}

union F2U { float2 f; unsigned long long u; };
__device__ __forceinline__ float2 f2fma(float2 a, float2 b, float2 c) {
    F2U A, B, C, R; A.f = a; B.f = b; C.f = c;
    asm("fma.rn.f32x2 %0, %1, %2, %3;" : "=l"(R.u) : "l"(A.u), "l"(B.u), "l"(C.u));
    return R.f;
}
__device__ __forceinline__ float2 f2mul(float2 a, float2 b) {
    F2U A, B, R; A.f = a; B.f = b;
    asm("mul.rn.f32x2 %0, %1, %2;" : "=l"(R.u) : "l"(A.u), "l"(B.u));
    return R.f;
}
__device__ __forceinline__ float2 f2add(float2 a, float2 b) {
    F2U A, B, R; A.f = a; B.f = b;
    asm("add.rn.f32x2 %0, %1, %2;" : "=l"(R.u) : "l"(A.u), "l"(B.u));
    return R.f;
}

// tanh-form GELU on a packed pair
__device__ __forceinline__ float2 gelu2(float2 x) {
    const float C1 = 0.7978845608028654f;            // sqrt(2/pi)
    const float C2 = 0.7978845608028654f * 0.044715f;
    float2 x2 = f2mul(x, x);
    float2 inner = f2fma(x2, make_float2(C2, C2), make_float2(C1, C1));
    float2 y  = f2mul(x, inner);
    float2 t  = make_float2(fast_tanh(y.x), fast_tanh(y.y));
    float2 phi = f2fma(t, make_float2(0.5f, 0.5f), make_float2(0.5f, 0.5f));
    return f2mul(x, phi);
}

struct WarpCtx {                 // LN affine folded into B1f/b1v at init
    unsigned B1f[2][4][2];
    unsigned B2f[4][2][2];
    float b1v[4][2];
    float2 b2p[2];
};

// Full tile compute: stats -> reduction -> LN -> GEMM1 -> GELU -> GEMM2 -> store.
__device__ __forceinline__ void tile_compute(const WarpCtx& W,
                                             float4 xa, float4 xb,
                                             float* __restrict__ orow,
                                             int g, int c)
{
    float2 xp[4] = { make_float2(xa.x, xb.x), make_float2(xa.y, xb.y),
                     make_float2(xa.z, xb.z), make_float2(xa.w, xb.w) };

    float2 s = f2add(f2add(xp[0], xp[1]), f2add(xp[2], xp[3]));
    float2 q = f2mul(xp[0], xp[0]);
    q = f2fma(xp[1], xp[1], q);
    q = f2fma(xp[2], xp[2], q);
    q = f2fma(xp[3], xp[3], q);

    s.x += __shfl_xor_sync(0xffffffffu, s.x, 1); s.x += __shfl_xor_sync(0xffffffffu, s.x, 2);
    s.y += __shfl_xor_sync(0xffffffffu, s.y, 1); s.y += __shfl_xor_sync(0xffffffffu, s.y, 2);
    q.x += __shfl_xor_sync(0xffffffffu, q.x, 1); q.x += __shfl_xor_sync(0xffffffffu, q.x, 2);
    q.y += __shfl_xor_sync(0xffffffffu, q.y, 1); q.y += __shfl_xor_sync(0xffffffffu, q.y, 2);

    const float inv = 1.0f / 16.0f;
    float2 mup = f2mul(s, make_float2(inv, inv));
    float2 qi  = f2mul(q, make_float2(inv, inv));
    float rstd0 = rsqrtf(fmaf(-mup.x, mup.x, qi.x) + 1e-5f);
    float rstd1 = rsqrtf(fmaf(-mup.y, mup.y, qi.y) + 1e-5f);
    float2 rstdp = make_float2(rstd0, rstd1);
    float2 nmup  = make_float2(-mup.x * rstd0, -mup.y * rstd1);

    // LN affine folded into weights: xn = (x - mu) * rstd only
    float2 xn[4];
    #pragma unroll
    for (int j = 0; j < 4; j++)
        xn[j] = f2fma(xp[j], rstdp, nmup);

    // GEMM1 (8 mma), seeded with folded b1'
    float C1[4][4];
    #pragma unroll
    for (int nt = 0; nt < 4; nt++) {
        C1[nt][0] = W.b1v[nt][0]; C1[nt][1] = W.b1v[nt][1];
        C1[nt][2] = W.b1v[nt][0]; C1[nt][3] = W.b1v[nt][1];
        mma8(C1[nt][0], C1[nt][1], C1[nt][2], C1[nt][3],
             bits(xn[0].x), bits(xn[0].y), bits(xn[1].x), bits(xn[1].y),
             W.B1f[0][nt][0], W.B1f[0][nt][1]);
        mma8(C1[nt][0], C1[nt][1], C1[nt][2], C1[nt][3],
             bits(xn[2].x), bits(xn[2].y), bits(xn[3].x), bits(xn[3].y),
             W.B1f[1][nt][0], W.B1f[1][nt][1]);
    }

    // GELU; C1 fragment IS the GEMM2 A fragment
    float2 ga[4], gb[4];
    #pragma unroll
    for (int kt = 0; kt < 4; kt++) {
        ga[kt] = gelu2(make_float2(C1[kt][0], C1[kt][1]));   // row g
        gb[kt] = gelu2(make_float2(C1[kt][2], C1[kt][3]));   // row g+8
    }

    // GEMM2 (8 mma), single accumulator seeded with b2 + residual
    float C2[2][4];
    {
        float2 s00 = f2add(W.b2p[0], make_float2(xa.x, xa.y));
        float2 s01 = f2add(W.b2p[1], make_float2(xa.z, xa.w));
        float2 s10 = f2add(W.b2p[0], make_float2(xb.x, xb.y));
        float2 s11 = f2add(W.b2p[1], make_float2(xb.z, xb.w));
        C2[0][0] = s00.x; C2[0][1] = s00.y; C2[0][2] = s10.x; C2[0][3] = s10.y;
        C2[1][0] = s01.x; C2[1][1] = s01.y; C2[1][2] = s11.x; C2[1][3] = s11.y;
    }
    #pragma unroll
    for (int nt = 0; nt < 2; nt++)
        #pragma unroll
        for (int kt = 0; kt < 4; kt++)
            mma8(C2[nt][0], C2[nt][1], C2[nt][2], C2[nt][3],
                 bits(ga[kt].x), bits(gb[kt].x), bits(ga[kt].y), bits(gb[kt].y),
                 W.B2f[kt][nt][0], W.B2f[kt][nt][1]);

    // streaming stores (evict-first): keep L2 capacity for the read stream
    stg_cs128(orow + g * DIM + 4 * c,       C2[0][0], C2[0][1], C2[1][0], C2[1][1]);
    stg_cs128(orow + (g + 8) * DIM + 4 * c, C2[0][2], C2[0][3], C2[1][2], C2[1][3]);
}

// One pipeline iteration, IT compile-time so wait_group count is a literal.
template<int IT>
__device__ __forceinline__ void pipe_iter(const WarpCtx& W,
                                          const char* __restrict__ xbase,
                                          float* __restrict__ obase,
                                          unsigned sbase,
                                          int lane, int g, int c)
{
    constexpr int NW = (TILES_PER_WARP - 1 - IT < DEPTH - 1) ? (TILES_PER_WARP - 1 - IT)
                                                             : (DEPTH - 1);
    cp_wait<NW>();

    const unsigned saddr = sbase + (IT % DEPTH) * TILE_BYTES + lane * 16;
    float4 xa = lds128(saddr);
    float4 xb = lds128(saddr + 512);

    if (IT + DEPTH < TILES_PER_WARP) {
        const char* ga = xbase + (size_t)(IT + DEPTH) * TILE_BYTES + lane * 16;
        unsigned sa = sbase + (IT % DEPTH) * TILE_BYTES + lane * 16;
        cp16(sa, ga);
        cp16(sa + 512, ga + 512);
        cp_commit();
    }

    tile_compute(W, xa, xb, obase + (size_t)IT * 16 * DIM, g, c);

    if constexpr (IT + 1 < TILES_PER_WARP)
        pipe_iter<IT + 1>(W, xbase, obase, sbase, lane, g, c);
}

// ---------------- kernel ----------------
__global__ void __launch_bounds__(TPB, 5)
fused_ln_mlp_mma(const float* __restrict__ x,
                 const float* __restrict__ ln_w, const float* __restrict__ ln_b,
                 const float* __restrict__ w1,   const float* __restrict__ b1,
                 const float* __restrict__ w2,   const float* __restrict__ b2,
                 float* __restrict__ out, int ntiles)
{
    __shared__ __align__(16) char stage[WARPS_PER_CTA][DEPTH * TILE_BYTES];

    const int lane = threadIdx.x & 31;
    const int wrp  = threadIdx.x >> 5;
    const int g = lane >> 2;
    const int c = lane & 3;

    WarpCtx W;
    {
        // raw w1 fragment values (this lane holds w1[nt*8+g][4c..4c+3])
        const float4 lw = *reinterpret_cast<const float4*>(ln_w + 4 * c);
        const float4 lb = *reinterpret_cast<const float4*>(ln_b + 4 * c);
        const float lnw[4] = { lw.x, lw.y, lw.z, lw.w };
        const float lnb[4] = { lb.x, lb.y, lb.z, lb.w };

        float dot[4];                       // Σ_d w1[nt*8+g][d] * ln_b[d] (partial)
        #pragma unroll
        for (int nt = 0; nt < 4; nt++) dot[nt] = 0.f;

        #pragma unroll
        for (int kt = 0; kt < 2; kt++)
            #pragma unroll
            for (int nt = 0; nt < 4; nt++) {
                float w0 = w1[(nt * 8 + g) * DIM + 4 * c + 2 * kt];
                float w1v = w1[(nt * 8 + g) * DIM + 4 * c + 2 * kt + 1];
                W.B1f[kt][nt][0] = tf32_rna(w0 * lnw[2 * kt]);       // fold ln_w
                W.B1f[kt][nt][1] = tf32_rna(w1v * lnw[2 * kt + 1]);
                dot[nt] = fmaf(w0, lnb[2 * kt], dot[nt]);            // fold ln_b
                dot[nt] = fmaf(w1v, lnb[2 * kt + 1], dot[nt]);
            }
        // quad-reduce dot over c -> full dot for hidden row nt*8+g
        #pragma unroll
        for (int nt = 0; nt < 4; nt++) {
            dot[nt] += __shfl_xor_sync(0xffffffffu, dot[nt], 1);
            dot[nt] += __shfl_xor_sync(0xffffffffu, dot[nt], 2);
        }
        // b1'[h] = b1[h] + dot[h]; this lane needs h = nt*8+2c and nt*8+2c+1
        #pragma unroll
        for (int nt = 0; nt < 4; nt++) {
            float d0 = __shfl_sync(0xffffffffu, dot[nt], 8 * c);       // g' = 2c
            float d1 = __shfl_sync(0xffffffffu, dot[nt], 8 * c + 4);   // g' = 2c+1
            W.b1v[nt][0] = b1[nt * 8 + 2 * c] + d0;
            W.b1v[nt][1] = b1[nt * 8 + 2 * c + 1] + d1;
        }
    }
    #pragma unroll
    for (int nt = 0; nt < 2; nt++) {
        int od = 4 * (g >> 1) + 2 * nt + (g & 1);
        #pragma unroll
        for (int kt = 0; kt < 4; kt++) {
            W.B2f[kt][nt][0] = tf32_rna(w2[od * HID + kt * 8 + 2 * c]);
            W.B2f[kt][nt][1] = tf32_rna(w2[od * HID + kt * 8 + 2 * c + 1]);
        }
    }
    #pragma unroll
    for (int nt = 0; nt < 2; nt++)
        W.b2p[nt] = make_float2(b2[4 * c + 2 * nt], b2[4 * c + 2 * nt + 1]);

    const int gwarp = blockIdx.x * WARPS_PER_CTA + wrp;
    const long t0 = (long)gwarp * TILES_PER_WARP;
    if (t0 >= ntiles) return;

    if (t0 + TILES_PER_WARP <= ntiles) {
        // ===== fast path: cp.async depth-6 pipeline, fully unrolled =====
        const char* xbase = reinterpret_cast<const char*>(x + (size_t)t0 * 16 * DIM);
        float* obase = out + (size_t)t0 * 16 * DIM;
        const unsigned sbase = smem_u32(&stage[wrp][0]);

        #pragma unroll
        for (int i = 0; i < DEPTH; i++) {
            unsigned sa = sbase + i * TILE_BYTES + lane * 16;
            const char* ga = xbase + (size_t)i * TILE_BYTES + lane * 16;
            cp16(sa, ga);
            cp16(sa + 512, ga + 512);
            cp_commit();
        }
        pipe_iter<0>(W, xbase, obase, sbase, lane, g, c);
    } else {
        // ===== tail path (generic, rarely taken) =====
        const int n_it = (int)(ntiles - t0);
        for (int it = 0; it < n_it; ++it) {
            const float4* p = reinterpret_cast<const float4*>(
                x + (size_t)(t0 + it) * 16 * DIM);
            float4 xa = p[lane], xb = p[lane + 32];
            tile_compute(W, xa, xb, out + (size_t)(t0 + it) * 16 * DIM, g, c);
        }
    }
}

extern "C" void kernel_launch(void* const* d_in, const int* in_sizes, int n_in,
                              void* d_out, int out_size)
{
    const float* x    = (const float*)d_in[0];
    const float* ln_w = (const float*)d_in[1];
    const float* ln_b = (const float*)d_in[2];
    const float* w1   = (const float*)d_in[3];
    const float* b1   = (const float*)d_in[4];
    const float* w2   = (const float*)d_in[5];
    const float* b2   = (const float*)d_in[6];
    int nrows  = in_sizes[0] / DIM;
    int ntiles = nrows / 16;
    int tiles_per_cta = WARPS_PER_CTA * TILES_PER_WARP;
    int blocks = (ntiles + tiles_per_cta - 1) / tiles_per_cta;
    fused_ln_mlp_mma<<<blocks, TPB>>>(x, ln_w, ln_b, w1, b1, w2, b2,
                                      (float*)d_out, ntiles);
}